// round 5
// baseline (speedup 1.0000x reference)
#include <cuda_runtime.h>
#include <cuda_bf16.h>
#include <cstdint>

// Problem constants: T=32768, E=256, K=8, D=8, r=2
#define E_EXPERTS 256
#define D_DEVS    8
#define K_TOPK    8
#define E_PER_DEV (E_EXPERTS / D_DEVS)   // 32
#define TOK_PER_BLK 64                   // 8 warps x 8 tokens

// Single fused kernel:
//   phase 0: issue meta loads (latency hidden under fill)
//   phase 1: zero this block's 64-token slice across all 8 device planes
//   phase 1b: block-local invperm (ballot rank) into smem
//   sync (block-wide fence: zeros visible to all warps in block)
//   phase 2: gather 2 selections/lane, scatter into own (zeroed) slice,
//            write 4 mask rows per warp as one coalesced 128B store
__global__ __launch_bounds__(256) void moe_remap_fused(
    const float* __restrict__ topk,     // [T, E]
    const int*   __restrict__ mapping,  // [E, D] one-hot
    const int*   __restrict__ meta,     // [T, K]
    float*       __restrict__ out,      // [D, T, 32]
    float*       __restrict__ mask,     // [T/2, D]
    int T)
{
    __shared__ int wcnt[8][8];
    __shared__ int invperm_s[E_EXPERTS];

    const int tid  = threadIdx.x;
    const int lane = tid & 31;
    const int warp = tid >> 5;
    const int wg   = blockIdx.x * 8 + warp;   // global warp id; owns 8 tokens
    const int t0   = wg * 8;
    const int blkT = blockIdx.x * TOK_PER_BLK;

    // ---- phase 0: kick off meta loads now (64 ints per warp, coalesced) ----
    const int e0 = meta[t0 * K_TOPK + lane];
    const int e1 = meta[t0 * K_TOPK + 32 + lane];

    // ---- phase 1b(i): expert->device + ballot counts (thread e = tid) ----
    {
        const int4* m4 = reinterpret_cast<const int4*>(mapping);
        const int4 a4 = m4[tid * 2];
        const int4 b4 = m4[tid * 2 + 1];
        int v[8] = {a4.x, a4.y, a4.z, a4.w, b4.x, b4.y, b4.z, b4.w};
        int best = v[0], d = 0;
#pragma unroll
        for (int i = 1; i < D_DEVS; i++)
            if (v[i] > best) { best = v[i]; d = i; }   // first max wins

        const unsigned lt = (1u << lane) - 1u;
        int within = 0, mycnt = 0;
#pragma unroll
        for (int d2 = 0; d2 < D_DEVS; d2++) {
            unsigned b = __ballot_sync(0xffffffffu, d == d2);
            if (d2 == d)    within = __popc(b & lt);
            if (lane == d2) mycnt  = __popc(b);
        }
        if (lane < D_DEVS) wcnt[warp][lane] = mycnt;

        // ---- phase 1: zero fill own slice (before sync) ----
        // 8 planes x 64 tokens x 32 floats = 4096 float4; 16 per thread.
        float4* o4 = reinterpret_cast<float4*>(out);
        const float4 z = make_float4(0.f, 0.f, 0.f, 0.f);
#pragma unroll
        for (int dd = 0; dd < D_DEVS; dd++) {
            const int base = dd * (T * (E_PER_DEV / 4)) + blkT * (E_PER_DEV / 4);
            o4[base + tid]       = z;
            o4[base + 256 + tid] = z;
        }

        __syncthreads();   // wcnt ready; fill stores fenced block-wide

        // ---- phase 1b(ii): rank -> invperm ----
        int off = 0;
#pragma unroll
        for (int w2 = 0; w2 < 8; w2++)
#pragma unroll
            for (int d2 = 0; d2 < D_DEVS; d2++) {
                int c = wcnt[w2][d2];
                off += ((d2 < d) || (d2 == d && w2 < warp)) ? c : 0;
            }
        invperm_s[tid] = off + within;
    }
    __syncthreads();       // invperm ready

    // ---- phase 2: gather + scatter (2 independent chains per lane) ----
    const int tl = lane >> 3;                                  // 0..3
    const float v0 = topk[(t0 + tl) * E_EXPERTS + e0];
    const float v1 = topk[(t0 + 4 + tl) * E_EXPERTS + e1];
    const int p0 = invperm_s[e0];
    const int p1 = invperm_s[e1];
    const int d0 = p0 >> 5, j0 = p0 & 31;
    const int d1 = p1 >> 5, j1 = p1 & 31;

    out[d0 * (T * E_PER_DEV) + (t0 + tl)     * E_PER_DEV + j0] = v0;
    out[d1 * (T * E_PER_DEV) + (t0 + 4 + tl) * E_PER_DEV + j1] = v1;

    // ---- masks: 4 pair rows per warp, packed dual butterfly ----
    unsigned m0 = 1u << d0;            // quad0 (tokens t0..t0+3)
    unsigned m1 = 1u << d1;            // quad1 (tokens t0+4..t0+7)
    unsigned mc = m0 | (m1 << 8);
#pragma unroll
    for (int o = 8; o; o >>= 1)
        mc |= __shfl_xor_sync(0xffffffffu, mc, o);   // OR within 16-lane halves

    const unsigned other = __shfl_xor_sync(0xffffffffu, mc, 16);
    const unsigned lo = (lane < 16) ? mc : other;    // pairs (0, 2)
    const unsigned hi = (lane < 16) ? other : mc;    // pairs (1, 3)

    const int pl = lane >> 3;          // pair-local 0..3
    const int dd = lane & 7;
    unsigned bits;
    if      (pl == 0) bits = lo & 0xffu;
    else if (pl == 1) bits = hi & 0xffu;
    else if (pl == 2) bits = (lo >> 8) & 0xffu;
    else              bits = (hi >> 8) & 0xffu;

    // pairs wg*4 .. wg*4+3  ->  mask floats [wg*32, wg*32+32): coalesced 128B
    mask[wg * 32 + lane] = ((bits >> dd) & 1u) ? 1.0f : 0.0f;
}

extern "C" void kernel_launch(void* const* d_in, const int* in_sizes, int n_in,
                              void* d_out, int out_size) {
    const float* topk    = (const float*)d_in[0];   // [1,1,T,E]
    const int*   mapping = (const int*)  d_in[1];   // [1,1,E,D]
    const int*   meta    = (const int*)  d_in[2];   // [1,1,T,K]

    const int T = in_sizes[0] / E_EXPERTS;          // 32768

    float* out  = (float*)d_out;                            // [D, T, 32]
    float* mask = out + (size_t)D_DEVS * T * E_PER_DEV;     // [T/2, D]

    const int blocks = T / TOK_PER_BLK;             // 512
    moe_remap_fused<<<blocks, 256>>>(topk, mapping, meta, out, mask, T);
}